// round 13
// baseline (speedup 1.0000x reference)
#include <cuda_runtime.h>
#include <cstdint>

// RoiPoolingConv v13: R8 body verbatim, occupancy cap lifted.
//   __launch_bounds__(128,16) -> 64 warps/SM theoretical (regs=40 fits:
//   40*128*16 = 82K < 256K). Single-variable experiment vs R8's (128,12):
//   in the latency/queue-mixed regime (no pipe > 61%), resident-warp count
//   is the remaining untapped resource.

__device__ __forceinline__ uint64_t pack2(float f) {
    uint64_t r; unsigned u = __float_as_uint(f);
    asm("mov.b64 %0, {%1,%1};" : "=l"(r) : "r"(u));
    return r;
}
__device__ __forceinline__ uint64_t fma2(uint64_t a, uint64_t b, uint64_t c) {
    uint64_t r;
    asm("fma.rn.f32x2 %0, %1, %2, %3;" : "=l"(r) : "l"(a), "l"(b), "l"(c));
    return r;
}
__device__ __forceinline__ uint64_t mul2(uint64_t a, uint64_t b) {
    uint64_t r;
    asm("mul.rn.f32x2 %0, %1, %2;" : "=l"(r) : "l"(a), "l"(b));
    return r;
}

struct V2 { uint64_t lo, hi; };

__device__ __forceinline__ V2 ldg2(const char* p) {
    V2 v;
    asm("ld.global.nc.v2.u64 {%0,%1}, [%2];"
        : "=l"(v.lo), "=l"(v.hi) : "l"(p));
    return v;
}
__device__ __forceinline__ void stcs2(char* p, uint64_t lo, uint64_t hi) {
    asm volatile("st.global.cs.v2.u64 [%0], {%1,%2};"
                 :: "l"(p), "l"(lo), "l"(hi) : "memory");
}

__device__ __forceinline__ void blend2(V2 a, V2 b, V2 d, V2 e,
                                       uint64_t W00, uint64_t W01,
                                       uint64_t W10, uint64_t W11,
                                       uint64_t& rlo, uint64_t& rhi)
{
    rlo = fma2(a.lo, W00, fma2(b.lo, W01, fma2(d.lo, W10, mul2(e.lo, W11))));
    rhi = fma2(a.hi, W00, fma2(b.hi, W01, fma2(d.hi, W10, mul2(e.hi, W11))));
}

__global__ void __launch_bounds__(128, 16)
roi_fused_kernel(const float* __restrict__ img,
                 const int*   __restrict__ rois,
                 float*       __restrict__ out,
                 int pool, int pp, unsigned magic, int W, int C4)
{
    const int r   = blockIdx.y;
    const int pir = blockIdx.x * 4 + (threadIdx.x >> 5);   // pixel in roi
    if (pir >= pp) return;
    const int c4  = threadIdx.x & 31;                      // chunks +0,32,64,96

    const int4 roi = __ldg(((const int4*)rois) + r);

    // pir < 4096: exact magic division by pool via 2^22
    const int py = (int)(((unsigned long long)pir * magic) >> 22);
    const int px = pir - py * pool;

    const float poolf = (float)pool;

    // y axis — fp32 sequence must match reference exactly up to the floor
    float hf     = (float)roi.w;
    float scaley = __fdiv_rn(hf, poolf);
    float sy     = __fsub_rn(__fmul_rn((float)py + 0.5f, scaley), 0.5f);
    sy = fminf(fmaxf(sy, 0.0f), hf - 1.0f);
    int   iy0 = (int)sy;
    int   iy1 = min(iy0 + 1, roi.w - 1);
    float fy  = sy - (float)iy0;

    // x axis
    float wf     = (float)roi.z;
    float scalex = __fdiv_rn(wf, poolf);
    float sx     = __fsub_rn(__fmul_rn((float)px + 0.5f, scalex), 0.5f);
    sx = fminf(fmaxf(sx, 0.0f), wf - 1.0f);
    int   ix0 = (int)sx;
    int   ix1 = min(ix0 + 1, roi.z - 1);
    float fx  = sx - (float)ix0;

    const int y0 = roi.y + iy0, y1 = roi.y + iy1;
    const int x0 = roi.x + ix0, x1 = roi.x + ix1;

    const float gx = 1.0f - fx, gy = 1.0f - fy;
    const uint64_t W00 = pack2(gx * gy), W01 = pack2(fx * gy);
    const uint64_t W10 = pack2(gx * fy), W11 = pack2(fx * fy);

    const char* base = (const char*)img;
    const char* pa = base + ((size_t)((y0 * W + x0) * C4 + c4) << 4);
    const char* pb = base + ((size_t)((y0 * W + x1) * C4 + c4) << 4);
    const char* pd = base + ((size_t)((y1 * W + x0) * C4 + c4) << 4);
    const char* pe = base + ((size_t)((y1 * W + x1) * C4 + c4) << 4);

    // 16 independent 128-bit loads (chunk stride 32 float4 = 512B)
    V2 a0 = ldg2(pa);          V2 b0 = ldg2(pb);
    V2 d0 = ldg2(pd);          V2 e0 = ldg2(pe);
    V2 a1 = ldg2(pa + 512);    V2 b1 = ldg2(pb + 512);
    V2 d1 = ldg2(pd + 512);    V2 e1 = ldg2(pe + 512);
    V2 a2 = ldg2(pa + 1024);   V2 b2 = ldg2(pb + 1024);
    V2 d2 = ldg2(pd + 1024);   V2 e2 = ldg2(pe + 1024);
    V2 a3 = ldg2(pa + 1536);   V2 b3 = ldg2(pb + 1536);
    V2 d3 = ldg2(pd + 1536);   V2 e3 = ldg2(pe + 1536);

    uint64_t r0lo, r0hi, r1lo, r1hi, r2lo, r2hi, r3lo, r3hi;
    blend2(a0, b0, d0, e0, W00, W01, W10, W11, r0lo, r0hi);
    blend2(a1, b1, d1, e1, W00, W01, W10, W11, r1lo, r1hi);
    blend2(a2, b2, d2, e2, W00, W01, W10, W11, r2lo, r2hi);
    blend2(a3, b3, d3, e3, W00, W01, W10, W11, r3lo, r3hi);

    char* o = (char*)out + ((size_t)((r * pp + pir) * C4 + c4) << 4);
    stcs2(o,        r0lo, r0hi);   // streaming: keep image L2-resident
    stcs2(o + 512,  r1lo, r1hi);
    stcs2(o + 1024, r2lo, r2hi);
    stcs2(o + 1536, r3lo, r3hi);
}

extern "C" void kernel_launch(void* const* d_in, const int* in_sizes, int n_in,
                              void* d_out, int out_size)
{
    const float* img  = (const float*)d_in[0];
    const int*   rois = (const int*)d_in[1];
    float*       out  = (float*)d_out;

    const int H = 128, W = 128;
    const int C        = in_sizes[0] / (H * W);      // 512
    const int num_rois = in_sizes[1] / 4;            // 256

    const int pp = out_size / (num_rois * C);        // pool^2 = 196
    int pool = 1;
    while (pool * pool < pp) pool++;                 // 14

    // magic for exact n/pool, n < 4096: m = ceil(2^22 / pool)
    unsigned magic = (unsigned)((4194304u + pool - 1) / pool);

    dim3 grid((pp + 3) / 4, num_rois);               // (49, 256) exact fit
    roi_fused_kernel<<<grid, 128>>>(img, rois, out, pool, pp, magic, W, C >> 2);
}

// round 14
// speedup vs baseline: 1.0538x; 1.0538x over previous
#include <cuda_runtime.h>
#include <cstdint>

// RoiPoolingConv v14: R8 structure with 256-bit memory ops (sm_100+).
//   Empirical width trend at constant line count: LDG.128x16 (28.3us) <
//   LDG.32x64 (30.0) < LDG.64x32 (35.7) -> fewer, wider memory instructions
//   win. This extends to LDG.256: lane = 32B chunk, 2 halves per thread:
//   8 x ld.global.nc.v4.u64 + 2 x st.global.cs.v4.u64 per thread
//   (vs R8's 16+4). Same bytes, same lines, same packed-FFMA2 count.

__device__ __forceinline__ uint64_t pack2(float f) {
    uint64_t r; unsigned u = __float_as_uint(f);
    asm("mov.b64 %0, {%1,%1};" : "=l"(r) : "r"(u));
    return r;
}
__device__ __forceinline__ uint64_t fma2(uint64_t a, uint64_t b, uint64_t c) {
    uint64_t r;
    asm("fma.rn.f32x2 %0, %1, %2, %3;" : "=l"(r) : "l"(a), "l"(b), "l"(c));
    return r;
}
__device__ __forceinline__ uint64_t mul2(uint64_t a, uint64_t b) {
    uint64_t r;
    asm("mul.rn.f32x2 %0, %1, %2;" : "=l"(r) : "l"(a), "l"(b));
    return r;
}

struct V4 { uint64_t x, y, z, w; };

// 256-bit load/store (sm_100+), 32B-aligned addresses.
__device__ __forceinline__ V4 ldg4(const char* p) {
    V4 v;
    asm("ld.global.nc.v4.u64 {%0,%1,%2,%3}, [%4];"
        : "=l"(v.x), "=l"(v.y), "=l"(v.z), "=l"(v.w) : "l"(p));
    return v;
}
__device__ __forceinline__ void stcs4(char* p, V4 v) {
    asm volatile("st.global.cs.v4.u64 [%0], {%1,%2,%3,%4};"
                 :: "l"(p), "l"(v.x), "l"(v.y), "l"(v.z), "l"(v.w) : "memory");
}

__device__ __forceinline__ V4 blend4(V4 a, V4 b, V4 d, V4 e,
                                     uint64_t W00, uint64_t W01,
                                     uint64_t W10, uint64_t W11)
{
    V4 r;
    r.x = fma2(a.x, W00, fma2(b.x, W01, fma2(d.x, W10, mul2(e.x, W11))));
    r.y = fma2(a.y, W00, fma2(b.y, W01, fma2(d.y, W10, mul2(e.y, W11))));
    r.z = fma2(a.z, W00, fma2(b.z, W01, fma2(d.z, W10, mul2(e.z, W11))));
    r.w = fma2(a.w, W00, fma2(b.w, W01, fma2(d.w, W10, mul2(e.w, W11))));
    return r;
}

__global__ void __launch_bounds__(128, 10)
roi_fused_kernel(const float* __restrict__ img,
                 const int*   __restrict__ rois,
                 float*       __restrict__ out,
                 int pool, int pp, unsigned magic, int W)
{
    const int r   = blockIdx.y;
    const int pir = blockIdx.x * 4 + (threadIdx.x >> 5);   // pixel in roi
    if (pir >= pp) return;
    const int c8  = threadIdx.x & 31;                      // 32B chunk lane

    const int4 roi = __ldg(((const int4*)rois) + r);

    // pir < 4096: exact magic division by pool via 2^22
    const int py = (int)(((unsigned long long)pir * magic) >> 22);
    const int px = pir - py * pool;

    const float poolf = (float)pool;

    // y axis — fp32 sequence must match reference exactly up to the floor
    float hf     = (float)roi.w;
    float scaley = __fdiv_rn(hf, poolf);
    float sy     = __fsub_rn(__fmul_rn((float)py + 0.5f, scaley), 0.5f);
    sy = fminf(fmaxf(sy, 0.0f), hf - 1.0f);
    int   iy0 = (int)sy;
    int   iy1 = min(iy0 + 1, roi.w - 1);
    float fy  = sy - (float)iy0;

    // x axis
    float wf     = (float)roi.z;
    float scalex = __fdiv_rn(wf, poolf);
    float sx     = __fsub_rn(__fmul_rn((float)px + 0.5f, scalex), 0.5f);
    sx = fminf(fmaxf(sx, 0.0f), wf - 1.0f);
    int   ix0 = (int)sx;
    int   ix1 = min(ix0 + 1, roi.z - 1);
    float fx  = sx - (float)ix0;

    const int y0 = roi.y + iy0, y1 = roi.y + iy1;
    const int x0 = roi.x + ix0, x1 = roi.x + ix1;

    const float gx = 1.0f - fx, gy = 1.0f - fy;
    const uint64_t W00 = pack2(gx * gy), W01 = pack2(fx * gy);
    const uint64_t W10 = pack2(gx * fy), W11 = pack2(fx * fy);

    // pixel stride = 512 floats = 2048B; lane chunk = 32B; halves at +0,+1024
    const char* base = (const char*)img + ((size_t)c8 << 5);
    const char* pa = base + (size_t)(y0 * W + x0) * 2048;
    const char* pb = base + (size_t)(y0 * W + x1) * 2048;
    const char* pd = base + (size_t)(y1 * W + x0) * 2048;
    const char* pe = base + (size_t)(y1 * W + x1) * 2048;

    // 8 independent 256-bit loads
    V4 a0 = ldg4(pa);          V4 b0 = ldg4(pb);
    V4 d0 = ldg4(pd);          V4 e0 = ldg4(pe);
    V4 a1 = ldg4(pa + 1024);   V4 b1 = ldg4(pb + 1024);
    V4 d1 = ldg4(pd + 1024);   V4 e1 = ldg4(pe + 1024);

    V4 r0 = blend4(a0, b0, d0, e0, W00, W01, W10, W11);
    V4 r1 = blend4(a1, b1, d1, e1, W00, W01, W10, W11);

    char* o = (char*)out + (size_t)(r * pp + pir) * 2048 + ((size_t)c8 << 5);
    stcs4(o,        r0);   // streaming: keep image L2-resident
    stcs4(o + 1024, r1);
}

extern "C" void kernel_launch(void* const* d_in, const int* in_sizes, int n_in,
                              void* d_out, int out_size)
{
    const float* img  = (const float*)d_in[0];
    const int*   rois = (const int*)d_in[1];
    float*       out  = (float*)d_out;

    const int H = 128, W = 128;
    const int C        = in_sizes[0] / (H * W);      // 512
    const int num_rois = in_sizes[1] / 4;            // 256

    const int pp = out_size / (num_rois * C);        // pool^2 = 196
    int pool = 1;
    while (pool * pool < pp) pool++;                 // 14

    // magic for exact n/pool, n < 4096: m = ceil(2^22 / pool)
    unsigned magic = (unsigned)((4194304u + pool - 1) / pool);

    dim3 grid((pp + 3) / 4, num_rois);               // (49, 256) exact fit
    roi_fused_kernel<<<grid, 128>>>(img, rois, out, pool, pp, magic, W);
}